// round 2
// baseline (speedup 1.0000x reference)
#include <cuda_runtime.h>

// EM-routing capsule layer, f32x2-packed fused streaming version.
// B=64, S=14, I=32 -> N=6272 per batch, C=10, D=16, 3 routing iterations.
//
// accum<IT>: one streaming pass over inputs_pose per iteration. Votes are
// recomputed in registers (packed f32x2, pairs over the p-dim). rr is
// recomputed from the previous iteration's tiny per-(b,c) statistics, which
// each CTA derives itself in a prologue from g_partial (finalize fused).
// Pose tiles are staged through swizzled smem (coalesced GMEM, conflict-free
// LDS), one barrier per spatial position.

#define BB   64
#define SSQ  196
#define II   32
#define CCL  10
#define KB   4        // spatial slices per batch
#define SPC  49       // 196/4 spatial positions per CTA
#define EPSf 1e-9f
#define PADZ 11

typedef unsigned long long u64;

__device__ float g_partial[BB * KB * CCL * 34]; // per (b,slice,c): [0]=rsum [1..16]=sv(pair) [17..32]=sv2(pair)

__device__ __forceinline__ u64 pack2(float lo, float hi) {
    u64 r; asm("mov.b64 %0,{%1,%2};" : "=l"(r) : "f"(lo), "f"(hi)); return r;
}
__device__ __forceinline__ void unpack2(u64 v, float& lo, float& hi) {
    asm("mov.b64 {%0,%1},%2;" : "=f"(lo), "=f"(hi) : "l"(v));
}
__device__ __forceinline__ u64 fma2(u64 a, u64 b, u64 c) {
    u64 d; asm("fma.rn.f32x2 %0,%1,%2,%3;" : "=l"(d) : "l"(a), "l"(b), "l"(c)); return d;
}
__device__ __forceinline__ u64 add2(u64 a, u64 b) {
    u64 d; asm("add.rn.f32x2 %0,%1,%2;" : "=l"(d) : "l"(a), "l"(b)); return d;
}
__device__ __forceinline__ u64 mul2(u64 a, u64 b) {
    u64 d; asm("mul.rn.f32x2 %0,%1,%2;" : "=l"(d) : "l"(a), "l"(b)); return d;
}

// d -> (pair j, hi) mapping: pairs are (r, r+4) for j=r<4 and (8+r, 12+r) for j=4+r
__device__ __forceinline__ int pair_slot(int d) {
    int j  = (d & 3) | ((d & 8) >> 1);
    int hi = (d >> 2) & 1;
    return 2 * j + hi;
}

template<int IT>
__global__ __launch_bounds__(320, 1)
void accum_kernel(const float* __restrict__ pose,
                  const float* __restrict__ act,
                  const float* __restrict__ w,
                  const float* __restrict__ beta_v,
                  const float* __restrict__ beta_a)
{
    __shared__ float4 s_tile[2][128];       // pose tile double buffer (swizzled)
    __shared__ float  s_act[2][32];
    __shared__ float  s_zz[2][32 * PADZ];   // [n_loc][c] stride 11
    __shared__ float  s_nms[CCL][16];       // -mean * sqrt(inv), pair layout
    __shared__ float  s_siv[CCL][16];       // sqrt(1/(2var+eps)), pair layout
    __shared__ float  s_cst[CCL];           // log(oact+eps) - sum log(stdv+eps)

    const int tid  = threadIdx.x;
    const int b    = blockIdx.x / KB;
    const int sl   = blockIdx.x % KB;
    const int c    = tid >> 5;   // warp = class
    const int lane = tid & 31;   // lane = capsule i

    // ---- prologue: derive stats of iteration IT-1 from partials (fused finalize) ----
    if (IT > 0) {
        if (tid < 160) {
            const int cc = tid >> 4, d = tid & 15;
            const int k = pair_slot(d);
            float rsum = 0.f, sv = 0.f, sv2 = 0.f;
            #pragma unroll
            for (int q = 0; q < KB; q++) {
                const float* p = g_partial + ((b * KB + q) * CCL + cc) * 34;
                rsum += p[0]; sv += p[1 + k]; sv2 += p[17 + k];
            }
            float mean = sv / rsum;
            float var  = fmaxf(sv2 / rsum - mean * mean, 0.f);
            float lg   = __logf(sqrtf(var) + EPSf);
            float cost = (beta_v[cc] + lg) * rsum;
            float lgs  = lg;
            #pragma unroll
            for (int off = 8; off; off >>= 1) {
                cost += __shfl_xor_sync(0xffffffffu, cost, off, 16);
                lgs  += __shfl_xor_sync(0xffffffffu, lgs,  off, 16);
            }
            const float invT = (float)IT;   // schedule for iteration IT-1: 1, 2
            float oact = 1.f / (1.f + __expf(-invT * (beta_a[cc] - cost)));
            float iv   = 1.f / (2.f * var + EPSf);
            float siv  = sqrtf(iv);
            s_nms[cc][k] = -mean * siv;
            s_siv[cc][k] = siv;
            if (d == 0) s_cst[cc] = __logf(oact + EPSf) - lgs;
        }
        __syncthreads();
    }

    // ---- per-thread constants ----
    u64 Wb[4][4];   // broadcast-packed W[i=lane][c][q][r]
    {
        const float* wr = w + (lane * CCL + c) * 16;
        #pragma unroll
        for (int q = 0; q < 4; q++)
            #pragma unroll
            for (int r = 0; r < 4; r++) { float x = wr[q * 4 + r]; Wb[q][r] = pack2(x, x); }
    }

    u64 nms[8], siv[8];
    float cstc = 0.f;
    if (IT > 0) {
        #pragma unroll
        for (int j = 0; j < 8; j++) {
            nms[j] = pack2(s_nms[c][2 * j], s_nms[c][2 * j + 1]);
            siv[j] = pack2(s_siv[c][2 * j], s_siv[c][2 * j + 1]);
        }
        cstc = s_cst[c];
    }

    u64 sv[8], sv2[8];
    #pragma unroll
    for (int j = 0; j < 8; j++) { sv[j] = 0ULL; sv2[j] = 0ULL; }
    float rsum = 0.f;

    const int s0 = sl * SPC;
    const float4* pose4 = reinterpret_cast<const float4*>(pose);

    // preload first tile
    {
        const int nb = (b * SSQ + s0) * II;
        if (tid < 128)      { int sx = tid ^ ((tid >> 3) & 7); s_tile[0][sx] = pose4[nb * 4 + tid]; }
        else if (tid < 160) { s_act[0][tid - 128] = act[nb + (tid - 128)]; }
    }
    __syncthreads();

    for (int k = 0; k < SPC; k++) {
        const int s   = s0 + k;
        const int cur = k & 1, nxt = cur ^ 1;

        // register-prefetch next tile (warps 0-4)
        float4 pf; float pa = 0.f;
        const bool doPf = (k + 1 < SPC);
        if (doPf) {
            const int nb = (b * SSQ + s + 1) * II;
            if (tid < 128)      pf = pose4[nb * 4 + tid];
            else if (tid < 160) pa = act[nb + (tid - 128)];
        }

        // pose row for this lane from swizzled smem
        float p16[16];
        #pragma unroll
        for (int q = 0; q < 4; q++) {
            int idx = lane * 4 + q;
            int sx  = idx ^ ((idx >> 3) & 7);
            float4 t = s_tile[cur][sx];
            p16[q * 4 + 0] = t.x; p16[q * 4 + 1] = t.y;
            p16[q * 4 + 2] = t.z; p16[q * 4 + 3] = t.w;
        }
        const float a = s_act[cur][lane];

        // votes: packed over p pairs (0,1) and (2,3); coord-add folded into init
        const int h  = s / 14;
        const int wx = s - h * 14;
        const float cr = (h  + 0.5f) * (1.0f / 14.0f);
        const float cw = (wx + 0.5f) * (1.0f / 14.0f);

        u64 Pq[2][4];
        #pragma unroll
        for (int q = 0; q < 4; q++) {
            Pq[0][q] = pack2(p16[q],     p16[4  + q]);
            Pq[1][q] = pack2(p16[8 + q], p16[12 + q]);
        }
        u64 v2[8];
        v2[0] = pack2(cr, 0.f);   // pair (d0, d4)
        v2[1] = pack2(cw, 0.f);   // pair (d1, d5)
        v2[2] = 0ULL; v2[3] = 0ULL; v2[4] = 0ULL; v2[5] = 0ULL; v2[6] = 0ULL; v2[7] = 0ULL;
        #pragma unroll
        for (int pp = 0; pp < 2; pp++)
            #pragma unroll
            for (int r = 0; r < 4; r++) {
                u64 acc = v2[pp * 4 + r];
                #pragma unroll
                for (int q = 0; q < 4; q++) acc = fma2(Pq[pp][q], Wb[q][r], acc);
                v2[pp * 4 + r] = acc;
            }

        if (IT > 0) {
            // zz = cst - sum_d ((v - m)*sqrt(inv))^2  -> 2 FMA2 per pair
            u64 az = 0ULL;
            #pragma unroll
            for (int j = 0; j < 8; j++) {
                u64 t = fma2(v2[j], siv[j], nms[j]);
                az = fma2(t, t, az);
            }
            float zlo, zhi; unpack2(az, zlo, zhi);
            s_zz[cur][lane * PADZ + c] = cstc - (zlo + zhi);
        }

        // store prefetched tile
        if (doPf) {
            if (tid < 128)      { int sx = tid ^ ((tid >> 3) & 7); s_tile[nxt][sx] = pf; }
            else if (tid < 160) s_act[nxt][tid - 128] = pa;
        }
        __syncthreads();   // zz visible + next tile ready (single barrier per s)

        float rrp;
        if (IT > 0) {
            // per-thread dense softmax over c (10 LDS + 10 exp, hidden under FMA)
            float z[CCL]; float mx = -1e30f;
            #pragma unroll
            for (int jc = 0; jc < CCL; jc++) {
                z[jc] = s_zz[cur][lane * PADZ + jc];
                mx = fmaxf(mx, z[jc]);
            }
            float Z = 0.f;
            #pragma unroll
            for (int jc = 0; jc < CCL; jc++) { float e = __expf(z[jc] - mx); z[jc] = e; Z += e; }
            rrp = __fdividef(z[c] * a, Z);
        } else {
            rrp = a * 0.1f;   // uniform rr = 1/C
        }

        rsum += rrp;
        const u64 rr2 = pack2(rrp, rrp);
        #pragma unroll
        for (int j = 0; j < 8; j++) {
            u64 rv = mul2(rr2, v2[j]);
            sv[j]  = add2(sv[j], rv);
            sv2[j] = fma2(rv, v2[j], sv2[j]);
        }
    }

    // reduce over the 32 lanes (capsule i)
    #pragma unroll
    for (int off = 16; off; off >>= 1) {
        rsum += __shfl_xor_sync(0xffffffffu, rsum, off);
        #pragma unroll
        for (int j = 0; j < 8; j++) {
            sv[j]  = add2(sv[j],  __shfl_xor_sync(0xffffffffu, sv[j],  off));
            sv2[j] = add2(sv2[j], __shfl_xor_sync(0xffffffffu, sv2[j], off));
        }
    }
    if (lane == 0) {
        float* o = g_partial + ((b * KB + sl) * CCL + c) * 34;
        o[0] = rsum;
        #pragma unroll
        for (int j = 0; j < 8; j++) {
            float lo, hi;
            unpack2(sv[j],  lo, hi); o[1  + 2 * j] = lo; o[2  + 2 * j] = hi;
            unpack2(sv2[j], lo, hi); o[17 + 2 * j] = lo; o[18 + 2 * j] = hi;
        }
    }
}

__global__ __launch_bounds__(160)
void finalize_out(const float* __restrict__ beta_v,
                  const float* __restrict__ beta_a,
                  float* __restrict__ out)
{
    const int b = blockIdx.x;
    const int c = threadIdx.x >> 4;
    const int d = threadIdx.x & 15;
    const int k = pair_slot(d);

    float rsum = 0.f, sv = 0.f, sv2 = 0.f;
    #pragma unroll
    for (int q = 0; q < KB; q++) {
        const float* p = g_partial + ((b * KB + q) * CCL + c) * 34;
        rsum += p[0]; sv += p[1 + k]; sv2 += p[17 + k];
    }
    float mean = sv / rsum;
    float var  = fmaxf(sv2 / rsum - mean * mean, 0.f);
    float lg   = __logf(sqrtf(var) + EPSf);
    float cost = (beta_v[c] + lg) * rsum;
    #pragma unroll
    for (int off = 8; off; off >>= 1)
        cost += __shfl_xor_sync(0xffffffffu, cost, off, 16);

    float oact = 1.f / (1.f + __expf(-3.0f * (beta_a[c] - cost)));   // invT = 3

    out[(b * CCL + c) * 16 + d] = mean;                    // pose [B,C,4,4]
    if (d == 0) out[BB * CCL * 16 + b * CCL + c] = oact;   // act  [B,C]
}

extern "C" void kernel_launch(void* const* d_in, const int* in_sizes, int n_in,
                              void* d_out, int out_size)
{
    const float* pose = (const float*)d_in[0];
    const float* act  = (const float*)d_in[1];
    const float* w    = (const float*)d_in[2];
    const float* bv   = (const float*)d_in[3];
    const float* ba   = (const float*)d_in[4];
    float* out = (float*)d_out;

    dim3 ga(BB * KB), ta(320), gf(BB), tf(160);

    accum_kernel<0><<<ga, ta>>>(pose, act, w, bv, ba);
    accum_kernel<1><<<ga, ta>>>(pose, act, w, bv, ba);
    accum_kernel<2><<<ga, ta>>>(pose, act, w, bv, ba);
    finalize_out<<<gf, tf>>>(bv, ba, out);
}

// round 3
// speedup vs baseline: 1.2677x; 1.2677x over previous
#include <cuda_runtime.h>

// EM-routing capsule layer. B=64, S=14, I=32 -> N=6272/batch, C=10, D=16, 3 iters.
//
// Pass 0 (uniform rr) is LINEARIZED: sum(a*v) = (sum a*p)@W and
// sum(a*v^2) = W^T (sum a*p^T p) W per capsule i, so it reduces to a cheap
// BW-bound reduction over pose + a tiny stats kernel. Passes 1-2 stream pose
// once each, recomputing votes in packed f32x2; rr from previous stats.

#define BB   64
#define SSQ  196
#define II   32
#define CCL  10
#define EPSf 1e-9f
#define L2E  1.4426950408889634f
#define PADZ 11

typedef unsigned long long u64;

__device__ float g0[128 * 10 * 69 * 32];        // pass0 per-(cta,warp) slabs, [f][i]-minor
__device__ float g_partial[128 * CCL * 34];     // per (b*2+half, c): [0]=rsum [1..16]=sv [17..32]=sv2
__device__ float g_stats[BB * CCL * 34];        // per (b,c): [0..15]=nms [16..31]=siv [32]=cst (log2 domain)

__device__ __forceinline__ u64 pack2(float lo, float hi) {
    u64 r; asm("mov.b64 %0,{%1,%2};" : "=l"(r) : "f"(lo), "f"(hi)); return r;
}
__device__ __forceinline__ void unpack2(u64 v, float& lo, float& hi) {
    asm("mov.b64 {%0,%1},%2;" : "=f"(lo), "=f"(hi) : "l"(v));
}
__device__ __forceinline__ u64 fma2(u64 a, u64 b, u64 c) {
    u64 d; asm("fma.rn.f32x2 %0,%1,%2,%3;" : "=l"(d) : "l"(a), "l"(b), "l"(c)); return d;
}
__device__ __forceinline__ u64 add2(u64 a, u64 b) {
    u64 d; asm("add.rn.f32x2 %0,%1,%2;" : "=l"(d) : "l"(a), "l"(b)); return d;
}
__device__ __forceinline__ u64 mul2(u64 a, u64 b) {
    u64 d; asm("mul.rn.f32x2 %0,%1,%2;" : "=l"(d) : "l"(a), "l"(b)); return d;
}
__device__ __forceinline__ float ex2f(float x) {
    float y; asm("ex2.approx.f32 %0,%1;" : "=f"(y) : "f"(x)); return y;
}

// ---------------- pass 0: linear/quadratic reduction over pose ----------------
__global__ __launch_bounds__(320, 1)
void pass0_kernel(const float* __restrict__ pose, const float* __restrict__ act)
{
    const int cta = blockIdx.x, b = cta >> 1, half = cta & 1;
    const int wpid = threadIdx.x >> 5, i = threadIdx.x & 31;

    float aP[16], G[40], X1[4], X2[4];
    float ra = 0.f, rc1 = 0.f, rc2 = 0.f, rq1 = 0.f, rq2 = 0.f;
    #pragma unroll
    for (int f = 0; f < 16; f++) aP[f] = 0.f;
    #pragma unroll
    for (int f = 0; f < 40; f++) G[f] = 0.f;
    #pragma unroll
    for (int f = 0; f < 4; f++) { X1[f] = 0.f; X2[f] = 0.f; }

    for (int sl = wpid; sl < 98; sl += 10) {
        const int s  = half * 98 + sl;
        const int h  = s / 14;
        const int wx = s - h * 14;
        const float cr = (h  + 0.5f) * (1.0f / 14.0f);
        const float cw = (wx + 0.5f) * (1.0f / 14.0f);

        const size_t nidx = ((size_t)(b * SSQ + s) * II + i);
        const float4* pv = reinterpret_cast<const float4*>(pose + nidx * 16);
        float p16[16];
        #pragma unroll
        for (int q4 = 0; q4 < 4; q4++) {
            float4 t = pv[q4];
            p16[q4*4+0] = t.x; p16[q4*4+1] = t.y; p16[q4*4+2] = t.z; p16[q4*4+3] = t.w;
        }
        const float a = act[nidx];

        #pragma unroll
        for (int p = 0; p < 4; p++) {
            float t0 = a * p16[p*4+0], t1 = a * p16[p*4+1];
            float t2 = a * p16[p*4+2], t3 = a * p16[p*4+3];
            aP[p*4+0] += t0; aP[p*4+1] += t1; aP[p*4+2] += t2; aP[p*4+3] += t3;
            float* Gp = G + p * 10;
            Gp[0] = fmaf(t0, p16[p*4+0], Gp[0]);
            Gp[1] = fmaf(t0, p16[p*4+1], Gp[1]);
            Gp[2] = fmaf(t0, p16[p*4+2], Gp[2]);
            Gp[3] = fmaf(t0, p16[p*4+3], Gp[3]);
            Gp[4] = fmaf(t1, p16[p*4+1], Gp[4]);
            Gp[5] = fmaf(t1, p16[p*4+2], Gp[5]);
            Gp[6] = fmaf(t1, p16[p*4+3], Gp[6]);
            Gp[7] = fmaf(t2, p16[p*4+2], Gp[7]);
            Gp[8] = fmaf(t2, p16[p*4+3], Gp[8]);
            Gp[9] = fmaf(t3, p16[p*4+3], Gp[9]);
        }
        ra += a;
        const float acr = a * cr, acw = a * cw;
        rc1 += acr; rc2 += acw;
        rq1 = fmaf(acr, cr, rq1); rq2 = fmaf(acw, cw, rq2);
        #pragma unroll
        for (int q = 0; q < 4; q++) {
            X1[q] = fmaf(acr, p16[q], X1[q]);
            X2[q] = fmaf(acw, p16[q], X2[q]);
        }
    }

    float* o = g0 + (size_t)(cta * 10 + wpid) * 69 * 32 + i;
    #pragma unroll
    for (int f = 0; f < 16; f++) o[f * 32] = aP[f];
    #pragma unroll
    for (int f = 0; f < 40; f++) o[(16 + f) * 32] = G[f];
    o[56 * 32] = ra;
    o[57 * 32] = rc1; o[58 * 32] = rc2;
    o[59 * 32] = rq1; o[60 * 32] = rq2;
    #pragma unroll
    for (int f = 0; f < 4; f++) { o[(61 + f) * 32] = X1[f]; o[(65 + f) * 32] = X2[f]; }
}

// ---------------- pass 0 stats: contract with W, produce g_stats ----------------
__global__ __launch_bounds__(320, 1)
void stats0_kernel(const float* __restrict__ wt,
                   const float* __restrict__ beta_v,
                   const float* __restrict__ beta_a)
{
    __shared__ float sm[32][72];
    const int b = blockIdx.x, tid = threadIdx.x;

    for (int t = tid; t < 32 * 69; t += 320) {
        const int i = t / 69, f = t - i * 69;
        float s = 0.f;
        #pragma unroll
        for (int k = 0; k < 20; k++) {
            const int cta = b * 2 + (k >= 10 ? 1 : 0);
            const int ww  = k - (k >= 10 ? 10 : 0);
            s += g0[(size_t)(cta * 10 + ww) * 69 * 32 + f * 32 + i];
        }
        sm[i][f] = s;
    }
    __syncthreads();

    if (tid < 160) {
        const int c = tid >> 4, d = tid & 15, p = d >> 2, r = d & 3;
        float RA = 0.f, RC = 0.f, RQ = 0.f, Sv = 0.f, Sv2 = 0.f, Cr = 0.f;
        for (int i = 0; i < 32; i++) {
            const float* g = sm[i];
            const float* wr = wt + (i * CCL + c) * 16;
            const float W0 = wr[0*4+r], W1 = wr[1*4+r], W2 = wr[2*4+r], W3 = wr[3*4+r];
            const float* ap = g + p * 4;
            Sv += ap[0]*W0 + ap[1]*W1 + ap[2]*W2 + ap[3]*W3;
            const float* Gp = g + 16 + p * 10;
            Sv2 += W0*W0*Gp[0] + W1*W1*Gp[4] + W2*W2*Gp[7] + W3*W3*Gp[9]
                 + 2.f*(W0*W1*Gp[1] + W0*W2*Gp[2] + W0*W3*Gp[3]
                      + W1*W2*Gp[5] + W1*W3*Gp[6] + W2*W3*Gp[8]);
            RA += g[56];
            if (d == 0) { RC += g[57]; RQ += g[59]; Cr += W0*g[61]+W1*g[62]+W2*g[63]+W3*g[64]; }
            else if (d == 1) { RC += g[58]; RQ += g[60]; Cr += W0*g[65]+W1*g[66]+W2*g[67]+W3*g[68]; }
        }
        float coordm = (d == 0 || d == 1) ? RC : 0.f;
        float coordv = (d == 0 || d == 1) ? (2.f * Cr + RQ) : 0.f;
        float mean = (Sv + coordm) / RA;
        float var  = fmaxf((Sv2 + coordv) / RA - mean * mean, 0.f);
        float lg   = __logf(sqrtf(var) + EPSf);
        float rr_sum = RA * 0.1f;
        float cost = (beta_v[c] + lg) * rr_sum, lgs = lg;
        #pragma unroll
        for (int off = 8; off; off >>= 1) {
            cost += __shfl_xor_sync(0xffffffffu, cost, off, 16);
            lgs  += __shfl_xor_sync(0xffffffffu, lgs,  off, 16);
        }
        float oact = 1.f / (1.f + __expf(-(beta_a[c] - cost)));   // invT = 1
        float siv  = sqrtf(L2E / (2.f * var + EPSf));
        float* st = g_stats + (b * CCL + c) * 34;
        st[d]      = -mean * siv;
        st[16 + d] = siv;
        if (d == 0) st[32] = (__logf(oact + EPSf) - lgs) * L2E;
    }
}

// ---------------- routing passes 1 and 2 (streaming, fused E+M) ----------------
template<int IT>
__global__ __launch_bounds__(320, 1)
void accum_kernel(const float* __restrict__ pose,
                  const float* __restrict__ act,
                  const float* __restrict__ wt,
                  const float* __restrict__ beta_v,
                  const float* __restrict__ beta_a)
{
    __shared__ float4 s_tile[2][256];
    __shared__ float  s_act[2][64];
    __shared__ float  s_zz[2][2][32 * PADZ];
    __shared__ float  s_st[CCL][33];

    const int cta = blockIdx.x, b = cta >> 1, half = cta & 1;
    const int tid = threadIdx.x, c = tid >> 5, lane = tid & 31;

    if (IT == 2) {   // derive stats of pass 1 from g_partial
        if (tid < 160) {
            const int cc = tid >> 4, d = tid & 15;
            float rsum = 0.f, sv = 0.f, sv2 = 0.f;
            #pragma unroll
            for (int q = 0; q < 2; q++) {
                const float* p = g_partial + ((b * 2 + q) * CCL + cc) * 34;
                rsum += p[0]; sv += p[1 + d]; sv2 += p[17 + d];
            }
            float mean = sv / rsum;
            float var  = fmaxf(sv2 / rsum - mean * mean, 0.f);
            float lg   = __logf(sqrtf(var) + EPSf);
            float cost = (beta_v[cc] + lg) * rsum, lgs = lg;
            #pragma unroll
            for (int off = 8; off; off >>= 1) {
                cost += __shfl_xor_sync(0xffffffffu, cost, off, 16);
                lgs  += __shfl_xor_sync(0xffffffffu, lgs,  off, 16);
            }
            float oact = 1.f / (1.f + __expf(-2.0f * (beta_a[cc] - cost)));  // invT = 2
            float siv  = sqrtf(L2E / (2.f * var + EPSf));
            s_st[cc][d]      = -mean * siv;
            s_st[cc][16 + d] = siv;
            if (d == 0) s_st[cc][32] = (__logf(oact + EPSf) - lgs) * L2E;
        }
        __syncthreads();
    }

    // W, r-paired: W2[q][rr] = (W[q][2rr], W[q][2rr+1]) -> 8 u64
    u64 W2[4][2];
    {
        const float* wr = wt + (lane * CCL + c) * 16;
        #pragma unroll
        for (int q = 0; q < 4; q++) {
            W2[q][0] = pack2(wr[q*4+0], wr[q*4+1]);
            W2[q][1] = pack2(wr[q*4+2], wr[q*4+3]);
        }
    }
    u64 nms[8], siv[8]; float cstc;
    if (IT == 1) {
        const float* st = g_stats + (b * CCL + c) * 34;
        #pragma unroll
        for (int j = 0; j < 8; j++) {
            nms[j] = pack2(st[2*j], st[2*j+1]);
            siv[j] = pack2(st[16+2*j], st[16+2*j+1]);
        }
        cstc = st[32];
    } else {
        #pragma unroll
        for (int j = 0; j < 8; j++) {
            nms[j] = pack2(s_st[c][2*j], s_st[c][2*j+1]);
            siv[j] = pack2(s_st[c][16+2*j], s_st[c][16+2*j+1]);
        }
        cstc = s_st[c][32];
    }

    u64 sv[8], sv2[8];
    #pragma unroll
    for (int j = 0; j < 8; j++) { sv[j] = 0ULL; sv2[j] = 0ULL; }
    float rsum = 0.f;

    const float4* pose4 = reinterpret_cast<const float4*>(pose);
    const size_t nb0 = ((size_t)(b * SSQ) + half * 98) * II;

    // preload tile 0 (s_loc 0,1)
    if (tid < 256) {
        const int soff = tid >> 7, idx = tid & 127, sx = idx ^ ((idx >> 3) & 7);
        s_tile[0][soff * 128 + sx] = pose4[(nb0 + soff * 32) * 4 + idx];
    } else {
        s_act[0][tid - 256] = act[nb0 + (tid - 256)];
    }
    __syncthreads();

    for (int k = 0; k < 49; k++) {
        const int cur = k & 1, nxt = cur ^ 1;

        float4 pf; float pa;
        const bool doPf = (k < 48);
        if (doPf) {
            const size_t nbn = nb0 + (size_t)(2 * k + 2) * II;
            if (tid < 256) pf = pose4[(nbn + (tid >> 7) * 32) * 4 + (tid & 127)];
            else           pa = act[nbn + (tid - 256)];
        }

        u64 v2[2][8];
        #pragma unroll
        for (int so = 0; so < 2; so++) {
            const int s  = half * 98 + 2 * k + so;
            const int h  = s / 14;
            const int wx = s - h * 14;

            float p16[16];
            #pragma unroll
            for (int q = 0; q < 4; q++) {
                const int idx = lane * 4 + q, sx = idx ^ ((idx >> 3) & 7);
                float4 t = s_tile[cur][so * 128 + sx];
                p16[q*4+0] = t.x; p16[q*4+1] = t.y; p16[q*4+2] = t.z; p16[q*4+3] = t.w;
            }

            v2[so][0] = pack2((h + 0.5f) * (1.0f/14.0f), (wx + 0.5f) * (1.0f/14.0f));
            #pragma unroll
            for (int j = 1; j < 8; j++) v2[so][j] = 0ULL;

            #pragma unroll
            for (int p = 0; p < 4; p++) {
                #pragma unroll
                for (int q = 0; q < 4; q++) {
                    const u64 pp = pack2(p16[p*4+q], p16[p*4+q]);
                    v2[so][p*2+0] = fma2(pp, W2[q][0], v2[so][p*2+0]);
                    v2[so][p*2+1] = fma2(pp, W2[q][1], v2[so][p*2+1]);
                }
            }

            // zz (log2 domain): cst - sum ((v-m)*siv)^2
            u64 az = 0ULL;
            #pragma unroll
            for (int j = 0; j < 8; j++) {
                u64 t = fma2(v2[so][j], siv[j], nms[j]);
                az = fma2(t, t, az);
            }
            float zlo, zhi; unpack2(az, zlo, zhi);
            s_zz[cur][so][lane * PADZ + c] = cstc - (zlo + zhi);
        }

        if (doPf) {
            if (tid < 256) {
                const int soff = tid >> 7, idx = tid & 127, sx = idx ^ ((idx >> 3) & 7);
                s_tile[nxt][soff * 128 + sx] = pf;
            } else {
                s_act[nxt][tid - 256] = pa;
            }
        }
        __syncthreads();   // zz visible + next tile staged

        #pragma unroll
        for (int so = 0; so < 2; so++) {
            const float a = s_act[cur][so * 32 + lane];
            float z[CCL], mx = -1e30f;
            #pragma unroll
            for (int jc = 0; jc < CCL; jc++) {
                z[jc] = s_zz[cur][so][lane * PADZ + jc];
                mx = fmaxf(mx, z[jc]);
            }
            float Z = 0.f, zc = 0.f;
            #pragma unroll
            for (int jc = 0; jc < CCL; jc++) {
                float e = ex2f(z[jc] - mx);
                if (jc == c) zc = e;
                Z += e;
            }
            const float rrp = __fdividef(zc * a, Z);
            rsum += rrp;
            const u64 rr2 = pack2(rrp, rrp);
            #pragma unroll
            for (int j = 0; j < 8; j++) {
                const u64 rv = mul2(rr2, v2[so][j]);
                sv[j]  = add2(sv[j], rv);
                sv2[j] = fma2(rv, v2[so][j], sv2[j]);
            }
        }
    }

    #pragma unroll
    for (int off = 16; off; off >>= 1) {
        rsum += __shfl_xor_sync(0xffffffffu, rsum, off);
        #pragma unroll
        for (int j = 0; j < 8; j++) {
            sv[j]  = add2(sv[j],  __shfl_xor_sync(0xffffffffu, sv[j],  off));
            sv2[j] = add2(sv2[j], __shfl_xor_sync(0xffffffffu, sv2[j], off));
        }
    }
    if (lane == 0) {
        float* o = g_partial + (cta * CCL + c) * 34;
        o[0] = rsum;
        #pragma unroll
        for (int j = 0; j < 8; j++) {
            float lo, hi;
            unpack2(sv[j],  lo, hi); o[1  + 2*j] = lo; o[2  + 2*j] = hi;
            unpack2(sv2[j], lo, hi); o[17 + 2*j] = lo; o[18 + 2*j] = hi;
        }
    }
}

// ---------------- final output ----------------
__global__ __launch_bounds__(160)
void finalize_out(const float* __restrict__ beta_v,
                  const float* __restrict__ beta_a,
                  float* __restrict__ out)
{
    const int b = blockIdx.x;
    const int c = threadIdx.x >> 4;
    const int d = threadIdx.x & 15;

    float rsum = 0.f, sv = 0.f, sv2 = 0.f;
    #pragma unroll
    for (int q = 0; q < 2; q++) {
        const float* p = g_partial + ((b * 2 + q) * CCL + c) * 34;
        rsum += p[0]; sv += p[1 + d]; sv2 += p[17 + d];
    }
    float mean = sv / rsum;
    float var  = fmaxf(sv2 / rsum - mean * mean, 0.f);
    float lg   = __logf(sqrtf(var) + EPSf);
    float cost = (beta_v[c] + lg) * rsum;
    #pragma unroll
    for (int off = 8; off; off >>= 1)
        cost += __shfl_xor_sync(0xffffffffu, cost, off, 16);

    float oact = 1.f / (1.f + __expf(-3.0f * (beta_a[c] - cost)));   // invT = 3

    out[(b * CCL + c) * 16 + d] = mean;
    if (d == 0) out[BB * CCL * 16 + b * CCL + c] = oact;
}

extern "C" void kernel_launch(void* const* d_in, const int* in_sizes, int n_in,
                              void* d_out, int out_size)
{
    const float* pose = (const float*)d_in[0];
    const float* act  = (const float*)d_in[1];
    const float* w    = (const float*)d_in[2];
    const float* bv   = (const float*)d_in[3];
    const float* ba   = (const float*)d_in[4];
    float* out = (float*)d_out;

    pass0_kernel <<<128, 320>>>(pose, act);
    stats0_kernel<<<64, 320>>>(w, bv, ba);
    accum_kernel<1><<<128, 320>>>(pose, act, w, bv, ba);
    accum_kernel<2><<<128, 320>>>(pose, act, w, bv, ba);
    finalize_out <<<64, 160>>>(bv, ba, out);
}

// round 5
// speedup vs baseline: 1.3225x; 1.0433x over previous
#include <cuda_runtime.h>

// EM-routing capsule layer. B=64, S=14, I=32 -> N=6272/batch, C=10, D=16, 3 iters.
// Pass 0 linearized (uniform rr => moments are linear/quadratic in pose).
// Passes 1-2 stream pose once each; grid=256 / 2 CTAs per SM for latency hiding.
// R5: fix s_act double-buffer race (read hoisted to pre-barrier region).

#define BB   64
#define SSQ  196
#define II   32
#define CCL  10
#define EPSf 1e-9f
#define L2E  1.4426950408889634f
#define PADZ 11

typedef unsigned long long u64;

__device__ float g0[128 * 10 * 69 * 32];        // pass0 per-(cta,warp) slabs, [f][i]-minor
__device__ float g_partial[256 * CCL * 34];     // per (b*4+sl, c): [0]=rsum [1..16]=sv [17..32]=sv2
__device__ float g_stats[BB * CCL * 34];        // per (b,c): [0..15]=nms [16..31]=siv [32]=cst (log2)

__device__ __forceinline__ u64 pack2(float lo, float hi) {
    u64 r; asm("mov.b64 %0,{%1,%2};" : "=l"(r) : "f"(lo), "f"(hi)); return r;
}
__device__ __forceinline__ void unpack2(u64 v, float& lo, float& hi) {
    asm("mov.b64 {%0,%1},%2;" : "=f"(lo), "=f"(hi) : "l"(v));
}
__device__ __forceinline__ u64 fma2(u64 a, u64 b, u64 c) {
    u64 d; asm("fma.rn.f32x2 %0,%1,%2,%3;" : "=l"(d) : "l"(a), "l"(b), "l"(c)); return d;
}
__device__ __forceinline__ u64 add2(u64 a, u64 b) {
    u64 d; asm("add.rn.f32x2 %0,%1,%2;" : "=l"(d) : "l"(a), "l"(b)); return d;
}
__device__ __forceinline__ u64 mul2(u64 a, u64 b) {
    u64 d; asm("mul.rn.f32x2 %0,%1,%2;" : "=l"(d) : "l"(a), "l"(b)); return d;
}
__device__ __forceinline__ float ex2f(float x) {
    float y; asm("ex2.approx.f32 %0,%1;" : "=f"(y) : "f"(x)); return y;
}

// ---------------- pass 0: linear/quadratic reduction over pose ----------------
__global__ __launch_bounds__(320, 1)
void pass0_kernel(const float* __restrict__ pose, const float* __restrict__ act)
{
    const int cta = blockIdx.x, b = cta >> 1, half = cta & 1;
    const int wpid = threadIdx.x >> 5, i = threadIdx.x & 31;

    float aP[16], G[40], X1[4], X2[4];
    float ra = 0.f, rc1 = 0.f, rc2 = 0.f, rq1 = 0.f, rq2 = 0.f;
    #pragma unroll
    for (int f = 0; f < 16; f++) aP[f] = 0.f;
    #pragma unroll
    for (int f = 0; f < 40; f++) G[f] = 0.f;
    #pragma unroll
    for (int f = 0; f < 4; f++) { X1[f] = 0.f; X2[f] = 0.f; }

    for (int sl = wpid; sl < 98; sl += 10) {
        const int s  = half * 98 + sl;
        const int h  = s / 14;
        const int wx = s - h * 14;
        const float cr = (h  + 0.5f) * (1.0f / 14.0f);
        const float cw = (wx + 0.5f) * (1.0f / 14.0f);

        const size_t nidx = ((size_t)(b * SSQ + s) * II + i);
        const float4* pv = reinterpret_cast<const float4*>(pose + nidx * 16);
        float p16[16];
        #pragma unroll
        for (int q4 = 0; q4 < 4; q4++) {
            float4 t = pv[q4];
            p16[q4*4+0] = t.x; p16[q4*4+1] = t.y; p16[q4*4+2] = t.z; p16[q4*4+3] = t.w;
        }
        const float a = act[nidx];

        #pragma unroll
        for (int p = 0; p < 4; p++) {
            float t0 = a * p16[p*4+0], t1 = a * p16[p*4+1];
            float t2 = a * p16[p*4+2], t3 = a * p16[p*4+3];
            aP[p*4+0] += t0; aP[p*4+1] += t1; aP[p*4+2] += t2; aP[p*4+3] += t3;
            float* Gp = G + p * 10;
            Gp[0] = fmaf(t0, p16[p*4+0], Gp[0]);
            Gp[1] = fmaf(t0, p16[p*4+1], Gp[1]);
            Gp[2] = fmaf(t0, p16[p*4+2], Gp[2]);
            Gp[3] = fmaf(t0, p16[p*4+3], Gp[3]);
            Gp[4] = fmaf(t1, p16[p*4+1], Gp[4]);
            Gp[5] = fmaf(t1, p16[p*4+2], Gp[5]);
            Gp[6] = fmaf(t1, p16[p*4+3], Gp[6]);
            Gp[7] = fmaf(t2, p16[p*4+2], Gp[7]);
            Gp[8] = fmaf(t2, p16[p*4+3], Gp[8]);
            Gp[9] = fmaf(t3, p16[p*4+3], Gp[9]);
        }
        ra += a;
        const float acr = a * cr, acw = a * cw;
        rc1 += acr; rc2 += acw;
        rq1 = fmaf(acr, cr, rq1); rq2 = fmaf(acw, cw, rq2);
        #pragma unroll
        for (int q = 0; q < 4; q++) {
            X1[q] = fmaf(acr, p16[q], X1[q]);
            X2[q] = fmaf(acw, p16[q], X2[q]);
        }
    }

    float* o = g0 + (size_t)(cta * 10 + wpid) * 69 * 32 + i;
    #pragma unroll
    for (int f = 0; f < 16; f++) o[f * 32] = aP[f];
    #pragma unroll
    for (int f = 0; f < 40; f++) o[(16 + f) * 32] = G[f];
    o[56 * 32] = ra;
    o[57 * 32] = rc1; o[58 * 32] = rc2;
    o[59 * 32] = rq1; o[60 * 32] = rq2;
    #pragma unroll
    for (int f = 0; f < 4; f++) { o[(61 + f) * 32] = X1[f]; o[(65 + f) * 32] = X2[f]; }
}

// ---------------- pass 0 stats: contract with W, produce g_stats ----------------
__global__ __launch_bounds__(320, 1)
void stats0_kernel(const float* __restrict__ wt,
                   const float* __restrict__ beta_v,
                   const float* __restrict__ beta_a)
{
    __shared__ float sm[32][72];
    const int b = blockIdx.x, tid = threadIdx.x;

    for (int t = tid; t < 32 * 69; t += 320) {
        const int i = t / 69, f = t - i * 69;
        float s = 0.f;
        #pragma unroll
        for (int k = 0; k < 20; k++) {
            const int cta = b * 2 + (k >= 10 ? 1 : 0);
            const int ww  = k - (k >= 10 ? 10 : 0);
            s += g0[(size_t)(cta * 10 + ww) * 69 * 32 + f * 32 + i];
        }
        sm[i][f] = s;
    }
    __syncthreads();

    if (tid < 160) {
        const int c = tid >> 4, d = tid & 15, p = d >> 2, r = d & 3;
        float RA = 0.f, RC = 0.f, RQ = 0.f, Sv = 0.f, Sv2 = 0.f, Cr = 0.f;
        for (int i = 0; i < 32; i++) {
            const float* g = sm[i];
            const float* wr = wt + (i * CCL + c) * 16;
            const float W0 = wr[0*4+r], W1 = wr[1*4+r], W2 = wr[2*4+r], W3 = wr[3*4+r];
            const float* ap = g + p * 4;
            Sv += ap[0]*W0 + ap[1]*W1 + ap[2]*W2 + ap[3]*W3;
            const float* Gp = g + 16 + p * 10;
            Sv2 += W0*W0*Gp[0] + W1*W1*Gp[4] + W2*W2*Gp[7] + W3*W3*Gp[9]
                 + 2.f*(W0*W1*Gp[1] + W0*W2*Gp[2] + W0*W3*Gp[3]
                      + W1*W2*Gp[5] + W1*W3*Gp[6] + W2*W3*Gp[8]);
            RA += g[56];
            if (d == 0) { RC += g[57]; RQ += g[59]; Cr += W0*g[61]+W1*g[62]+W2*g[63]+W3*g[64]; }
            else if (d == 1) { RC += g[58]; RQ += g[60]; Cr += W0*g[65]+W1*g[66]+W2*g[67]+W3*g[68]; }
        }
        float coordm = (d == 0 || d == 1) ? RC : 0.f;
        float coordv = (d == 0 || d == 1) ? (2.f * Cr + RQ) : 0.f;
        float mean = (Sv + coordm) / RA;
        float var  = fmaxf((Sv2 + coordv) / RA - mean * mean, 0.f);
        float lg   = __logf(sqrtf(var) + EPSf);
        float rr_sum = RA * 0.1f;
        float cost = (beta_v[c] + lg) * rr_sum, lgs = lg;
        #pragma unroll
        for (int off = 8; off; off >>= 1) {
            cost += __shfl_xor_sync(0xffffffffu, cost, off, 16);
            lgs  += __shfl_xor_sync(0xffffffffu, lgs,  off, 16);
        }
        float oact = 1.f / (1.f + __expf(-(beta_a[c] - cost)));   // invT = 1
        float siv  = sqrtf(L2E / (2.f * var + EPSf));
        float* st = g_stats + (b * CCL + c) * 34;
        st[d]      = -mean * siv;
        st[16 + d] = siv;
        if (d == 0) st[32] = (__logf(oact + EPSf) - lgs) * L2E;
    }
}

// ---------------- routing passes 1 and 2 (streaming, fused E+M) ----------------
template<int IT>
__global__ __launch_bounds__(320, 2)
void accum_kernel(const float* __restrict__ pose,
                  const float* __restrict__ act,
                  const float* __restrict__ wt,
                  const float* __restrict__ beta_v,
                  const float* __restrict__ beta_a)
{
    __shared__ float4 s_tile[2][128];
    __shared__ float  s_act[2][32];
    __shared__ float  s_zz[2][32 * PADZ];
    __shared__ u64    s_nms[CCL][8];     // (-m*siv) packed pairs (d,d+1)
    __shared__ u64    s_siv[CCL][8];
    __shared__ float  s_cst[CCL];
    __shared__ float2 s_coord[49];

    const int cta = blockIdx.x, b = cta >> 2, sl = cta & 3;
    const int tid = threadIdx.x, c = tid >> 5, lane = tid & 31;
    const int s0 = sl * 49;

    // ---- stats into smem ----
    if (tid < 160) {
        const int cc = tid >> 4, d = tid & 15;
        float nmsv, sivv, cstv = 0.f;
        if (IT == 1) {
            const float* st = g_stats + (b * CCL + cc) * 34;
            nmsv = st[d]; sivv = st[16 + d];
            if (d == 0) cstv = st[32];
        } else {
            float rsum = 0.f, sv = 0.f, sv2 = 0.f;
            #pragma unroll
            for (int q = 0; q < 4; q++) {
                const float* p = g_partial + ((b * 4 + q) * CCL + cc) * 34;
                rsum += p[0]; sv += p[1 + d]; sv2 += p[17 + d];
            }
            float mean = sv / rsum;
            float var  = fmaxf(sv2 / rsum - mean * mean, 0.f);
            float lg   = __logf(sqrtf(var) + EPSf);
            float cost = (beta_v[cc] + lg) * rsum, lgs = lg;
            #pragma unroll
            for (int off = 8; off; off >>= 1) {
                cost += __shfl_xor_sync(0xffffffffu, cost, off, 16);
                lgs  += __shfl_xor_sync(0xffffffffu, lgs,  off, 16);
            }
            float oact = 1.f / (1.f + __expf(-2.0f * (beta_a[cc] - cost)));  // invT = 2
            sivv = sqrtf(L2E / (2.f * var + EPSf));
            nmsv = -mean * sivv;
            if (d == 0) cstv = (__logf(oact + EPSf) - lgs) * L2E;
        }
        reinterpret_cast<float*>(s_nms[cc])[d] = nmsv;
        reinterpret_cast<float*>(s_siv[cc])[d] = sivv;
        if (d == 0) s_cst[cc] = cstv;
    } else if (tid >= 256 && tid < 305) {
        const int s = s0 + (tid - 256);
        const int h = s / 14, wx = s - h * 14;
        s_coord[tid - 256] = make_float2((h + 0.5f) * (1.0f/14.0f), (wx + 0.5f) * (1.0f/14.0f));
    }
    __syncthreads();

    // W, r-paired: W2[q][rr] = (W[q][2rr], W[q][2rr+1])
    u64 W2[4][2];
    {
        const float* wr = wt + (lane * CCL + c) * 16;
        #pragma unroll
        for (int q = 0; q < 4; q++) {
            W2[q][0] = pack2(wr[q*4+0], wr[q*4+1]);
            W2[q][1] = pack2(wr[q*4+2], wr[q*4+3]);
        }
    }
    const float cstc = s_cst[c];

    u64 sv[8], sv2[8];
    #pragma unroll
    for (int j = 0; j < 8; j++) { sv[j] = 0ULL; sv2[j] = 0ULL; }
    float rsum = 0.f;

    const float4* pose4 = reinterpret_cast<const float4*>(pose);
    const size_t nb0 = ((size_t)(b * SSQ) + s0) * II;

    // preload tile 0
    if (tid < 128)      { const int sx = tid ^ ((tid >> 3) & 7); s_tile[0][sx] = pose4[nb0 * 4 + tid]; }
    else if (tid < 160) { s_act[0][tid - 128] = act[nb0 + (tid - 128)]; }
    __syncthreads();

    for (int k = 0; k < 49; k++) {
        const int cur = k & 1, nxt = cur ^ 1;

        float4 pf; float pa;
        const bool doPf = (k < 48);
        if (doPf) {
            const size_t nbn = nb0 + (size_t)(k + 1) * II;
            if (tid < 128)      pf = pose4[nbn * 4 + tid];
            else if (tid < 160) pa = act[nbn + (tid - 128)];
        }

        // pose row + activation from smem — BOTH read pre-barrier (race fix)
        float p16[16];
        #pragma unroll
        for (int q = 0; q < 4; q++) {
            const int idx = lane * 4 + q, sx = idx ^ ((idx >> 3) & 7);
            float4 t = s_tile[cur][sx];
            p16[q*4+0] = t.x; p16[q*4+1] = t.y; p16[q*4+2] = t.z; p16[q*4+3] = t.w;
        }
        const float a = s_act[cur][lane];   // MUST be pre-barrier: next iter overwrites this buffer

        // votes, r-paired; coords folded into init of pair (d0,d1)
        const float2 cc2 = s_coord[k];
        u64 v2[8];
        v2[0] = pack2(cc2.x, cc2.y);
        #pragma unroll
        for (int j = 1; j < 8; j++) v2[j] = 0ULL;
        #pragma unroll
        for (int p = 0; p < 4; p++) {
            #pragma unroll
            for (int q = 0; q < 4; q++) {
                const u64 pp = pack2(p16[p*4+q], p16[p*4+q]);
                v2[p*2+0] = fma2(pp, W2[q][0], v2[p*2+0]);
                v2[p*2+1] = fma2(pp, W2[q][1], v2[p*2+1]);
            }
        }

        // zz (log2): cst - sum ((v-m)*siv)^2 ; stats from broadcast smem
        u64 az = 0ULL;
        #pragma unroll
        for (int j = 0; j < 8; j++) {
            u64 t = fma2(v2[j], s_siv[c][j], s_nms[c][j]);
            az = fma2(t, t, az);
        }
        float zlo, zhi; unpack2(az, zlo, zhi);
        s_zz[cur][lane * PADZ + c] = cstc - (zlo + zhi);

        if (doPf) {
            if (tid < 128)      { const int sx = tid ^ ((tid >> 3) & 7); s_tile[nxt][sx] = pf; }
            else if (tid < 160) s_act[nxt][tid - 128] = pa;
        }
        __syncthreads();   // zz visible + next tile staged

        // streamed softmax over classes (broadcast smem reads)
        const float* zrow = &s_zz[cur][lane * PADZ];
        float mx = zrow[0];
        #pragma unroll
        for (int jc = 1; jc < CCL; jc++) mx = fmaxf(mx, zrow[jc]);
        float Z = 0.f;
        #pragma unroll
        for (int jc = 0; jc < CCL; jc++) Z += ex2f(zrow[jc] - mx);
        const float zc = ex2f(zrow[c] - mx);
        const float rrp = __fdividef(zc * a, Z);

        rsum += rrp;
        const u64 rr2 = pack2(rrp, rrp);
        #pragma unroll
        for (int j = 0; j < 8; j++) {
            const u64 rv = mul2(rr2, v2[j]);
            sv[j]  = add2(sv[j], rv);
            sv2[j] = fma2(rv, v2[j], sv2[j]);
        }
    }

    #pragma unroll
    for (int off = 16; off; off >>= 1) {
        rsum += __shfl_xor_sync(0xffffffffu, rsum, off);
        #pragma unroll
        for (int j = 0; j < 8; j++) {
            sv[j]  = add2(sv[j],  __shfl_xor_sync(0xffffffffu, sv[j],  off));
            sv2[j] = add2(sv2[j], __shfl_xor_sync(0xffffffffu, sv2[j], off));
        }
    }
    if (lane == 0) {
        float* o = g_partial + (cta * CCL + c) * 34;
        o[0] = rsum;
        #pragma unroll
        for (int j = 0; j < 8; j++) {
            float lo, hi;
            unpack2(sv[j],  lo, hi); o[1  + 2*j] = lo; o[2  + 2*j] = hi;
            unpack2(sv2[j], lo, hi); o[17 + 2*j] = lo; o[18 + 2*j] = hi;
        }
    }
}

// ---------------- final output ----------------
__global__ __launch_bounds__(160)
void finalize_out(const float* __restrict__ beta_v,
                  const float* __restrict__ beta_a,
                  float* __restrict__ out)
{
    const int b = blockIdx.x;
    const int c = threadIdx.x >> 4;
    const int d = threadIdx.x & 15;

    float rsum = 0.f, sv = 0.f, sv2 = 0.f;
    #pragma unroll
    for (int q = 0; q < 4; q++) {
        const float* p = g_partial + ((b * 4 + q) * CCL + c) * 34;
        rsum += p[0]; sv += p[1 + d]; sv2 += p[17 + d];
    }
    float mean = sv / rsum;
    float var  = fmaxf(sv2 / rsum - mean * mean, 0.f);
    float lg   = __logf(sqrtf(var) + EPSf);
    float cost = (beta_v[c] + lg) * rsum;
    #pragma unroll
    for (int off = 8; off; off >>= 1)
        cost += __shfl_xor_sync(0xffffffffu, cost, off, 16);

    float oact = 1.f / (1.f + __expf(-3.0f * (beta_a[c] - cost)));   // invT = 3

    out[(b * CCL + c) * 16 + d] = mean;
    if (d == 0) out[BB * CCL * 16 + b * CCL + c] = oact;
}

extern "C" void kernel_launch(void* const* d_in, const int* in_sizes, int n_in,
                              void* d_out, int out_size)
{
    const float* pose = (const float*)d_in[0];
    const float* act  = (const float*)d_in[1];
    const float* w    = (const float*)d_in[2];
    const float* bv   = (const float*)d_in[3];
    const float* ba   = (const float*)d_in[4];
    float* out = (float*)d_out;

    pass0_kernel <<<128, 320>>>(pose, act);
    stats0_kernel<<<64, 320>>>(w, bv, ba);
    accum_kernel<1><<<256, 320>>>(pose, act, w, bv, ba);
    accum_kernel<2><<<256, 320>>>(pose, act, w, bv, ba);
    finalize_out <<<64, 160>>>(bv, ba, out);
}

// round 6
// speedup vs baseline: 1.4004x; 1.0589x over previous
#include <cuda_runtime.h>

// EM-routing capsule layer. B=64, S=14, I=32 -> N=6272/batch, C=10, D=16, 3 iters.
// Pass 0 linearized; passes 1-2 stream pose once each, 2 CTAs/SM.
// R6: self-shifted softmax (no max, no numerator ex2), vectorized zz reads,
//     float4-interleaved stats (1 LDS.128 per d-pair), hoisted swizzle indices.

#define BB   64
#define SSQ  196
#define II   32
#define CCL  10
#define EPSf 1e-9f
#define L2E  1.4426950408889634f

typedef unsigned long long u64;

__device__ float g0[128 * 10 * 69 * 32];        // pass0 per-(cta,warp) slabs, [f][i]-minor
__device__ float g_partial[256 * CCL * 34];     // per (b*4+sl, c): [0]=rsum [1..16]=sv [17..32]=sv2
__device__ float g_stats[BB * CCL * 34];        // per (b,c): [0..15]=nms [16..31]=siv [32]=cst (log2)

__device__ __forceinline__ u64 pack2(float lo, float hi) {
    u64 r; asm("mov.b64 %0,{%1,%2};" : "=l"(r) : "f"(lo), "f"(hi)); return r;
}
__device__ __forceinline__ void unpack2(u64 v, float& lo, float& hi) {
    asm("mov.b64 {%0,%1},%2;" : "=f"(lo), "=f"(hi) : "l"(v));
}
__device__ __forceinline__ u64 fma2(u64 a, u64 b, u64 c) {
    u64 d; asm("fma.rn.f32x2 %0,%1,%2,%3;" : "=l"(d) : "l"(a), "l"(b), "l"(c)); return d;
}
__device__ __forceinline__ u64 add2(u64 a, u64 b) {
    u64 d; asm("add.rn.f32x2 %0,%1,%2;" : "=l"(d) : "l"(a), "l"(b)); return d;
}
__device__ __forceinline__ u64 mul2(u64 a, u64 b) {
    u64 d; asm("mul.rn.f32x2 %0,%1,%2;" : "=l"(d) : "l"(a), "l"(b)); return d;
}
__device__ __forceinline__ float ex2f(float x) {
    float y; asm("ex2.approx.f32 %0,%1;" : "=f"(y) : "f"(x)); return y;
}

// ---------------- pass 0: linear/quadratic reduction over pose ----------------
__global__ __launch_bounds__(320, 1)
void pass0_kernel(const float* __restrict__ pose, const float* __restrict__ act)
{
    const int cta = blockIdx.x, b = cta >> 1, half = cta & 1;
    const int wpid = threadIdx.x >> 5, i = threadIdx.x & 31;

    float aP[16], G[40], X1[4], X2[4];
    float ra = 0.f, rc1 = 0.f, rc2 = 0.f, rq1 = 0.f, rq2 = 0.f;
    #pragma unroll
    for (int f = 0; f < 16; f++) aP[f] = 0.f;
    #pragma unroll
    for (int f = 0; f < 40; f++) G[f] = 0.f;
    #pragma unroll
    for (int f = 0; f < 4; f++) { X1[f] = 0.f; X2[f] = 0.f; }

    for (int sl = wpid; sl < 98; sl += 10) {
        const int s  = half * 98 + sl;
        const int h  = s / 14;
        const int wx = s - h * 14;
        const float cr = (h  + 0.5f) * (1.0f / 14.0f);
        const float cw = (wx + 0.5f) * (1.0f / 14.0f);

        const size_t nidx = ((size_t)(b * SSQ + s) * II + i);
        const float4* pv = reinterpret_cast<const float4*>(pose + nidx * 16);
        float p16[16];
        #pragma unroll
        for (int q4 = 0; q4 < 4; q4++) {
            float4 t = pv[q4];
            p16[q4*4+0] = t.x; p16[q4*4+1] = t.y; p16[q4*4+2] = t.z; p16[q4*4+3] = t.w;
        }
        const float a = act[nidx];

        #pragma unroll
        for (int p = 0; p < 4; p++) {
            float t0 = a * p16[p*4+0], t1 = a * p16[p*4+1];
            float t2 = a * p16[p*4+2], t3 = a * p16[p*4+3];
            aP[p*4+0] += t0; aP[p*4+1] += t1; aP[p*4+2] += t2; aP[p*4+3] += t3;
            float* Gp = G + p * 10;
            Gp[0] = fmaf(t0, p16[p*4+0], Gp[0]);
            Gp[1] = fmaf(t0, p16[p*4+1], Gp[1]);
            Gp[2] = fmaf(t0, p16[p*4+2], Gp[2]);
            Gp[3] = fmaf(t0, p16[p*4+3], Gp[3]);
            Gp[4] = fmaf(t1, p16[p*4+1], Gp[4]);
            Gp[5] = fmaf(t1, p16[p*4+2], Gp[5]);
            Gp[6] = fmaf(t1, p16[p*4+3], Gp[6]);
            Gp[7] = fmaf(t2, p16[p*4+2], Gp[7]);
            Gp[8] = fmaf(t2, p16[p*4+3], Gp[8]);
            Gp[9] = fmaf(t3, p16[p*4+3], Gp[9]);
        }
        ra += a;
        const float acr = a * cr, acw = a * cw;
        rc1 += acr; rc2 += acw;
        rq1 = fmaf(acr, cr, rq1); rq2 = fmaf(acw, cw, rq2);
        #pragma unroll
        for (int q = 0; q < 4; q++) {
            X1[q] = fmaf(acr, p16[q], X1[q]);
            X2[q] = fmaf(acw, p16[q], X2[q]);
        }
    }

    float* o = g0 + (size_t)(cta * 10 + wpid) * 69 * 32 + i;
    #pragma unroll
    for (int f = 0; f < 16; f++) o[f * 32] = aP[f];
    #pragma unroll
    for (int f = 0; f < 40; f++) o[(16 + f) * 32] = G[f];
    o[56 * 32] = ra;
    o[57 * 32] = rc1; o[58 * 32] = rc2;
    o[59 * 32] = rq1; o[60 * 32] = rq2;
    #pragma unroll
    for (int f = 0; f < 4; f++) { o[(61 + f) * 32] = X1[f]; o[(65 + f) * 32] = X2[f]; }
}

// ---------------- pass 0 stats: contract with W, produce g_stats ----------------
__global__ __launch_bounds__(320, 1)
void stats0_kernel(const float* __restrict__ wt,
                   const float* __restrict__ beta_v,
                   const float* __restrict__ beta_a)
{
    __shared__ float sm[32][72];
    const int b = blockIdx.x, tid = threadIdx.x;

    for (int t = tid; t < 32 * 69; t += 320) {
        const int i = t / 69, f = t - i * 69;
        float s = 0.f;
        #pragma unroll
        for (int k = 0; k < 20; k++) {
            const int cta = b * 2 + (k >= 10 ? 1 : 0);
            const int ww  = k - (k >= 10 ? 10 : 0);
            s += g0[(size_t)(cta * 10 + ww) * 69 * 32 + f * 32 + i];
        }
        sm[i][f] = s;
    }
    __syncthreads();

    if (tid < 160) {
        const int c = tid >> 4, d = tid & 15, p = d >> 2, r = d & 3;
        float RA = 0.f, RC = 0.f, RQ = 0.f, Sv = 0.f, Sv2 = 0.f, Cr = 0.f;
        for (int i = 0; i < 32; i++) {
            const float* g = sm[i];
            const float* wr = wt + (i * CCL + c) * 16;
            const float W0 = wr[0*4+r], W1 = wr[1*4+r], W2 = wr[2*4+r], W3 = wr[3*4+r];
            const float* ap = g + p * 4;
            Sv += ap[0]*W0 + ap[1]*W1 + ap[2]*W2 + ap[3]*W3;
            const float* Gp = g + 16 + p * 10;
            Sv2 += W0*W0*Gp[0] + W1*W1*Gp[4] + W2*W2*Gp[7] + W3*W3*Gp[9]
                 + 2.f*(W0*W1*Gp[1] + W0*W2*Gp[2] + W0*W3*Gp[3]
                      + W1*W2*Gp[5] + W1*W3*Gp[6] + W2*W3*Gp[8]);
            RA += g[56];
            if (d == 0) { RC += g[57]; RQ += g[59]; Cr += W0*g[61]+W1*g[62]+W2*g[63]+W3*g[64]; }
            else if (d == 1) { RC += g[58]; RQ += g[60]; Cr += W0*g[65]+W1*g[66]+W2*g[67]+W3*g[68]; }
        }
        float coordm = (d == 0 || d == 1) ? RC : 0.f;
        float coordv = (d == 0 || d == 1) ? (2.f * Cr + RQ) : 0.f;
        float mean = (Sv + coordm) / RA;
        float var  = fmaxf((Sv2 + coordv) / RA - mean * mean, 0.f);
        float lg   = __logf(sqrtf(var) + EPSf);
        float rr_sum = RA * 0.1f;
        float cost = (beta_v[c] + lg) * rr_sum, lgs = lg;
        #pragma unroll
        for (int off = 8; off; off >>= 1) {
            cost += __shfl_xor_sync(0xffffffffu, cost, off, 16);
            lgs  += __shfl_xor_sync(0xffffffffu, lgs,  off, 16);
        }
        float oact = 1.f / (1.f + __expf(-(beta_a[c] - cost)));   // invT = 1
        float siv  = sqrtf(L2E / (2.f * var + EPSf));
        float* st = g_stats + (b * CCL + c) * 34;
        st[d]      = -mean * siv;
        st[16 + d] = siv;
        if (d == 0) st[32] = (__logf(oact + EPSf) - lgs) * L2E;
    }
}

// ---------------- routing passes 1 and 2 (streaming, fused E+M) ----------------
template<int IT>
__global__ __launch_bounds__(320, 2)
void accum_kernel(const float* __restrict__ pose,
                  const float* __restrict__ act,
                  const float* __restrict__ wt,
                  const float* __restrict__ beta_v,
                  const float* __restrict__ beta_a)
{
    __shared__ float4 s_tile[2][128];
    __shared__ float  s_act[2][32];
    __shared__ float  s_zz[2][320];                        // [lane*10 + c], stride 10
    __shared__ __align__(16) float s_stat[CCL][8][4];      // per pair j: nms0,nms1,siv0,siv1
    __shared__ float  s_cst[CCL];
    __shared__ float2 s_coord[49];

    const int cta = blockIdx.x, b = cta >> 2, sl = cta & 3;
    const int tid = threadIdx.x, c = tid >> 5, lane = tid & 31;
    const int s0 = sl * 49;

    // ---- stats into smem ----
    if (tid < 160) {
        const int cc = tid >> 4, d = tid & 15;
        float nmsv, sivv, cstv = 0.f;
        if (IT == 1) {
            const float* st = g_stats + (b * CCL + cc) * 34;
            nmsv = st[d]; sivv = st[16 + d];
            if (d == 0) cstv = st[32];
        } else {
            float rsum = 0.f, sv = 0.f, sv2 = 0.f;
            #pragma unroll
            for (int q = 0; q < 4; q++) {
                const float* p = g_partial + ((b * 4 + q) * CCL + cc) * 34;
                rsum += p[0]; sv += p[1 + d]; sv2 += p[17 + d];
            }
            float mean = sv / rsum;
            float var  = fmaxf(sv2 / rsum - mean * mean, 0.f);
            float lg   = __logf(sqrtf(var) + EPSf);
            float cost = (beta_v[cc] + lg) * rsum, lgs = lg;
            #pragma unroll
            for (int off = 8; off; off >>= 1) {
                cost += __shfl_xor_sync(0xffffffffu, cost, off, 16);
                lgs  += __shfl_xor_sync(0xffffffffu, lgs,  off, 16);
            }
            float oact = 1.f / (1.f + __expf(-2.0f * (beta_a[cc] - cost)));  // invT = 2
            sivv = sqrtf(L2E / (2.f * var + EPSf));
            nmsv = -mean * sivv;
            if (d == 0) cstv = (__logf(oact + EPSf) - lgs) * L2E;
        }
        s_stat[cc][d >> 1][d & 1]       = nmsv;
        s_stat[cc][d >> 1][2 + (d & 1)] = sivv;
        if (d == 0) s_cst[cc] = cstv;
    } else if (tid >= 256 && tid < 305) {
        const int s = s0 + (tid - 256);
        const int h = s / 14, wx = s - h * 14;
        s_coord[tid - 256] = make_float2((h + 0.5f) * (1.0f/14.0f), (wx + 0.5f) * (1.0f/14.0f));
    }
    __syncthreads();

    // W, r-paired: W2[q][rr] = (W[q][2rr], W[q][2rr+1])
    u64 W2[4][2];
    {
        const float* wr = wt + (lane * CCL + c) * 16;
        #pragma unroll
        for (int q = 0; q < 4; q++) {
            W2[q][0] = pack2(wr[q*4+0], wr[q*4+1]);
            W2[q][1] = pack2(wr[q*4+2], wr[q*4+3]);
        }
    }
    const float cstc = s_cst[c];
    const unsigned stat_base = (unsigned)__cvta_generic_to_shared(&s_stat[c][0][0]);

    // loop-invariant swizzled pose indices
    int sxq[4];
    #pragma unroll
    for (int q = 0; q < 4; q++) {
        const int idx = lane * 4 + q;
        sxq[q] = idx ^ ((idx >> 3) & 7);
    }

    u64 sv[8], sv2[8];
    #pragma unroll
    for (int j = 0; j < 8; j++) { sv[j] = 0ULL; sv2[j] = 0ULL; }
    float rsum = 0.f;

    const float4* pose4 = reinterpret_cast<const float4*>(pose);
    const size_t nb0 = ((size_t)(b * SSQ) + s0) * II;

    // preload tile 0
    if (tid < 128)      { const int sx = tid ^ ((tid >> 3) & 7); s_tile[0][sx] = pose4[nb0 * 4 + tid]; }
    else if (tid < 160) { s_act[0][tid - 128] = act[nb0 + (tid - 128)]; }
    __syncthreads();

    for (int k = 0; k < 49; k++) {
        const int cur = k & 1, nxt = cur ^ 1;

        float4 pf; float pa;
        const bool doPf = (k < 48);
        if (doPf) {
            const size_t nbn = nb0 + (size_t)(k + 1) * II;
            if (tid < 128)      pf = pose4[nbn * 4 + tid];
            else if (tid < 160) pa = act[nbn + (tid - 128)];
        }

        // pose row + activation (both pre-barrier; buffers overwritten next iter)
        float p16[16];
        #pragma unroll
        for (int q = 0; q < 4; q++) {
            float4 t = s_tile[cur][sxq[q]];
            p16[q*4+0] = t.x; p16[q*4+1] = t.y; p16[q*4+2] = t.z; p16[q*4+3] = t.w;
        }
        const float a = s_act[cur][lane];

        // votes, r-paired; coords folded into init of pair (d0,d1)
        const float2 cc2 = s_coord[k];
        u64 v2[8];
        v2[0] = pack2(cc2.x, cc2.y);
        #pragma unroll
        for (int j = 1; j < 8; j++) v2[j] = 0ULL;
        #pragma unroll
        for (int p = 0; p < 4; p++) {
            #pragma unroll
            for (int q = 0; q < 4; q++) {
                const u64 pp = pack2(p16[p*4+q], p16[p*4+q]);
                v2[p*2+0] = fma2(pp, W2[q][0], v2[p*2+0]);
                v2[p*2+1] = fma2(pp, W2[q][1], v2[p*2+1]);
            }
        }

        // zz (log2): cst - sum ((v-m)*siv)^2 ; stats via one LDS.128 per pair
        u64 az = 0ULL;
        #pragma unroll
        for (int j = 0; j < 8; j++) {
            u64 nm, sviv;
            asm volatile("ld.shared.v2.b64 {%0,%1},[%2];"
                         : "=l"(nm), "=l"(sviv) : "r"(stat_base + 16u * j));
            u64 t = fma2(v2[j], sviv, nm);
            az = fma2(t, t, az);
        }
        float zlo, zhi; unpack2(az, zlo, zhi);
        const float zc = cstc - (zlo + zhi);   // kept in register for self-shift
        s_zz[cur][lane * 10 + c] = zc;

        if (doPf) {
            if (tid < 128)      { const int sx = tid ^ ((tid >> 3) & 7); s_tile[nxt][sx] = pf; }
            else if (tid < 160) s_act[nxt][tid - 128] = pa;
        }
        __syncthreads();   // zz visible + next tile staged

        // self-shifted softmax: rr = a / sum_j exp2(z_j - z_c); j=c term = 1
        const float2* zr = reinterpret_cast<const float2*>(&s_zz[cur][lane * 10]);
        float Z = 0.f;
        #pragma unroll
        for (int j5 = 0; j5 < 5; j5++) {
            float2 zp = zr[j5];
            Z += ex2f(zp.x - zc);
            Z += ex2f(zp.y - zc);
        }
        const float rrp = __fdividef(a, Z);

        rsum += rrp;
        const u64 rr2 = pack2(rrp, rrp);
        #pragma unroll
        for (int j = 0; j < 8; j++) {
            const u64 rv = mul2(rr2, v2[j]);
            sv[j]  = add2(sv[j], rv);
            sv2[j] = fma2(rv, v2[j], sv2[j]);
        }
    }

    #pragma unroll
    for (int off = 16; off; off >>= 1) {
        rsum += __shfl_xor_sync(0xffffffffu, rsum, off);
        #pragma unroll
        for (int j = 0; j < 8; j++) {
            sv[j]  = add2(sv[j],  __shfl_xor_sync(0xffffffffu, sv[j],  off));
            sv2[j] = add2(sv2[j], __shfl_xor_sync(0xffffffffu, sv2[j], off));
        }
    }
    if (lane == 0) {
        float* o = g_partial + (cta * CCL + c) * 34;
        o[0] = rsum;
        #pragma unroll
        for (int j = 0; j < 8; j++) {
            float lo, hi;
            unpack2(sv[j],  lo, hi); o[1  + 2*j] = lo; o[2  + 2*j] = hi;
            unpack2(sv2[j], lo, hi); o[17 + 2*j] = lo; o[18 + 2*j] = hi;
        }
    }
}

// ---------------- final output ----------------
__global__ __launch_bounds__(160)
void finalize_out(const float* __restrict__ beta_v,
                  const float* __restrict__ beta_a,
                  float* __restrict__ out)
{
    const int b = blockIdx.x;
    const int c = threadIdx.x >> 4;
    const int d = threadIdx.x & 15;

    float rsum = 0.f, sv = 0.f, sv2 = 0.f;
    #pragma unroll
    for (int q = 0; q < 4; q++) {
        const float* p = g_partial + ((b * 4 + q) * CCL + c) * 34;
        rsum += p[0]; sv += p[1 + d]; sv2 += p[17 + d];
    }
    float mean = sv / rsum;
    float var  = fmaxf(sv2 / rsum - mean * mean, 0.f);
    float lg   = __logf(sqrtf(var) + EPSf);
    float cost = (beta_v[c] + lg) * rsum;
    #pragma unroll
    for (int off = 8; off; off >>= 1)
        cost += __shfl_xor_sync(0xffffffffu, cost, off, 16);

    float oact = 1.f / (1.f + __expf(-3.0f * (beta_a[c] - cost)));   // invT = 3

    out[(b * CCL + c) * 16 + d] = mean;
    if (d == 0) out[BB * CCL * 16 + b * CCL + c] = oact;
}

extern "C" void kernel_launch(void* const* d_in, const int* in_sizes, int n_in,
                              void* d_out, int out_size)
{
    const float* pose = (const float*)d_in[0];
    const float* act  = (const float*)d_in[1];
    const float* w    = (const float*)d_in[2];
    const float* bv   = (const float*)d_in[3];
    const float* ba   = (const float*)d_in[4];
    float* out = (float*)d_out;

    pass0_kernel <<<128, 320>>>(pose, act);
    stats0_kernel<<<64, 320>>>(w, bv, ba);
    accum_kernel<1><<<256, 320>>>(pose, act, w, bv, ba);
    accum_kernel<2><<<256, 320>>>(pose, act, w, bv, ba);
    finalize_out <<<64, 160>>>(bv, ba, out);
}